// round 13
// baseline (speedup 1.0000x reference)
#include <cuda_runtime.h>
#include <cuda_bf16.h>

// Problem constants (match setup_inputs: P=1024, M=64, R=64)
#define P 1024
#define MDIM 64
#define RDIM 64
#define NTHR 256
#define PF 2       // software-pipeline depth (float4 buffers in flight)
#define QJ  256    // j's per stream block (quarter row)
#define NPRE    (P / 8)   // 128 precompute blocks at the FRONT of the grid
#define NSTREAM (P * 4)   // 4096 stream blocks

// hsum tiling
#define ITILE 8
#define JTILE 128
#define NJT   (P / JTILE)   // 8
#define NIT   (P / ITILE)   // 128

// Allocation-free scratch (__device__ globals)
__device__ float g_hi[P];
__device__ float g_hj[P];
__device__ float g_mx[P];
__device__ float g_inv[P];
__device__ float g_attn[P * P];   // 4 MB: RAW dots (rela . Wr)
__device__ int   g_rowcnt[P];     // quarters-done per row (reset by hsum)
__device__ int   g_pre;           // precompute-ready counter (reset by hsum)

// ---------------------------------------------------------------------------
// Kernel A: one grid, three roles.
//   blocks [0, 128):    precompute hi/hj (warp-per-row), zero d_out, then
//                       signal g_pre. Wave-1 guaranteed (front of grid),
//                       never waits -> no deadlock possible.
//   blocks [128, 4224): block = (row i, quarter q). Streams 64 KB of rela via
//                       __ldcs, writes 256 RAW dot values. The block that
//                       completes a row's 4th quarter computes that row's
//                       softmax stats (mx, 1/sum) from L2 — hidden under the
//                       DRAM stream of the remaining blocks.
// ---------------------------------------------------------------------------
__global__ __launch_bounds__(NTHR, 8) void stream_kernel(
    const float* __restrict__ rela,
    const float* __restrict__ hidden,
    const int*   __restrict__ nei,
    const float* __restrict__ W,
    const float* __restrict__ bptr,
    float* __restrict__ out)
{
    const int tid  = threadIdx.x;
    const int warp = tid >> 5;
    const int lane = tid & 31;

    if (blockIdx.x < NPRE) {
        // ---- precompute branch: hi/hj + zero d_out + ready signal ----
        const int pid = blockIdx.x;
        const int row = pid * 8 + warp;
        const int gid = pid * 256 + tid;             // 32768 threads

        reinterpret_cast<float2*>(out)[gid] = make_float2(0.0f, 0.0f);

        float2 h = reinterpret_cast<const float2*>(hidden + (size_t)row * MDIM)[lane];
        float wi0 = W[RDIM + lane * 2];
        float wi1 = W[RDIM + lane * 2 + 1];
        float wj0 = W[RDIM + MDIM + lane * 2];
        float wj1 = W[RDIM + MDIM + lane * 2 + 1];

        float si = h.x * wi0 + h.y * wi1;
        float sj = h.x * wj0 + h.y * wj1;
        #pragma unroll
        for (int off = 16; off >= 1; off >>= 1) {
            si += __shfl_xor_sync(0xFFFFFFFFu, si, off);
            sj += __shfl_xor_sync(0xFFFFFFFFu, sj, off);
        }
        if (lane == 0) {
            g_hi[row] = si;
            g_hj[row] = sj;
        }
        __threadfence();
        __syncthreads();
        if (tid == 0) atomicAdd(&g_pre, 1);
        return;
    }

    // ---- streaming branch ----
    __shared__ float part[QJ * 5];       // 4 partials per local j, padded (5 KB)
    __shared__ float red[8];
    __shared__ int   s_old;

    const int half = (lane >> 4);
    const int lh   = lane & 15;          // lane within half-warp
    const int hwid = warp * 2 + half;    // 0..15 half-warp id

    const int sid = blockIdx.x - NPRE;
    const int i   = sid >> 2;
    const int q   = sid & 3;
    const int j0  = q * QJ;

    {
        const float4 wv = __ldg(&reinterpret_cast<const float4*>(W)[lh]);
        // iteration k handles local j = k*16 + hwid; this thread reads float4 #lh
        const float4* p = reinterpret_cast<const float4*>(rela + (size_t)i * (P * RDIM))
                        + (size_t)(j0 + hwid) * 16 + lh;
        // stride per k: 16 j's * 16 float4 = 256 float4
        float4 buf[PF];
        #pragma unroll
        for (int qq = 0; qq < PF; qq++) buf[qq] = __ldcs(p + qq * 256);
        p += PF * 256;

        #pragma unroll
        for (int kk = 0; kk < (QJ / 16) / PF; kk++) {
            #pragma unroll
            for (int qq = 0; qq < PF; qq++) {
                float4 v = buf[qq];
                if (kk < (QJ / 16) / PF - 1) buf[qq] = __ldcs(p + qq * 256);
                float s = fmaf(v.x, wv.x, fmaf(v.y, wv.y, fmaf(v.z, wv.z, v.w * wv.w)));
                s += __shfl_xor_sync(0xFFFFFFFFu, s, 8);     // 16 -> 8
                s += __shfl_xor_sync(0xFFFFFFFFu, s, 4);     // 8 -> 4 partials
                const int jl = (kk * PF + qq) * 16 + hwid;
                if (lh < 4) part[jl * 5 + lh] = s;           // conflict-free (pad 5)
            }
            p += PF * 256;
        }
    }
    __syncthreads();

    // ---- finish: thread tid <-> local j = tid; write RAW dot ----
    {
        const float* pj = &part[tid * 5];          // stride 5: conflict-free
        float s = (pj[0] + pj[1]) + (pj[2] + pj[3]);
        g_attn[(size_t)i * P + j0 + tid] = s;      // coalesced 1 KB
    }

    // ---- quarter done: maybe compute row stats (threadFenceReduction pattern)
    __threadfence();
    __syncthreads();
    if (tid == 0) s_old = atomicAdd(&g_rowcnt[i], 1);
    __syncthreads();
    if (s_old != 3) return;

    // This block completed the row: wait for hi/hj (wave-1 producers), then
    // compute mx and 1/sum for row i from L2-resident raw dots.
    if (tid == 0) {
        while (*(volatile int*)&g_pre < NPRE) __nanosleep(64);
    }
    __syncthreads();
    __threadfence();

    float4 v  = reinterpret_cast<const float4*>(g_attn + (size_t)i * P)[tid];
    int4  n4  = reinterpret_cast<const int4*>(nei + (size_t)i * P)[tid];
    float4 hj = reinterpret_cast<const float4*>(g_hj)[tid];
    const float hb = g_hi[i] + bptr[0];

    v.x = (n4.x > 0) ? (v.x + hj.x + hb) : 0.0f;  if (v.x == 0.0f) v.x = -1e-6f;
    v.y = (n4.y > 0) ? (v.y + hj.y + hb) : 0.0f;  if (v.y == 0.0f) v.y = -1e-6f;
    v.z = (n4.z > 0) ? (v.z + hj.z + hb) : 0.0f;  if (v.z == 0.0f) v.z = -1e-6f;
    v.w = (n4.w > 0) ? (v.w + hj.w + hb) : 0.0f;  if (v.w == 0.0f) v.w = -1e-6f;

    float mx = fmaxf(fmaxf(v.x, v.y), fmaxf(v.z, v.w));
    #pragma unroll
    for (int off = 16; off >= 1; off >>= 1)
        mx = fmaxf(mx, __shfl_xor_sync(0xFFFFFFFFu, mx, off));
    if (lane == 0) red[warp] = mx;
    __syncthreads();
    {
        float m = red[0];
        #pragma unroll
        for (int w = 1; w < 8; w++) m = fmaxf(m, red[w]);
        mx = m;
    }
    __syncthreads();

    float sum = __expf(v.x - mx) + __expf(v.y - mx)
              + __expf(v.z - mx) + __expf(v.w - mx);
    #pragma unroll
    for (int off = 16; off >= 1; off >>= 1)
        sum += __shfl_xor_sync(0xFFFFFFFFu, sum, off);
    if (lane == 0) red[warp] = sum;
    __syncthreads();
    if (tid == 0) {
        float s = 0.0f;
        #pragma unroll
        for (int w = 0; w < 8; w++) s += red[w];
        g_mx[i]  = mx;
        g_inv[i] = 1.0f / s;
    }
}

// ---------------------------------------------------------------------------
// Kernel B: H_sum = attn @ hidden with attn computed ON THE FLY from raw dots
// + row stats during tile staging. 128 i-tiles (8 rows) x 8 j-tiles = 1024
// blocks. Also resets the counters for the next graph replay.
// ---------------------------------------------------------------------------
__global__ __launch_bounds__(NTHR) void hsum_kernel(
    const float* __restrict__ hidden,
    const int*   __restrict__ nei,
    const float* __restrict__ bptr,
    float*       __restrict__ out)
{
    __shared__ float sat[ITILE][JTILE];          // 4 KB (attn tile)
    __shared__ float partb[4][ITILE][MDIM];      // 8 KB

    const int tid = threadIdx.x;
    const int it  = blockIdx.x >> 3;          // 0..127
    const int jt  = blockIdx.x & 7;           // 0..7
    const int i0  = it * ITILE;
    const int j0  = jt * JTILE;

    // reset counters for the next replay (this kernel always runs last)
    if (jt == 0 && tid < ITILE) g_rowcnt[i0 + tid] = 0;
    if (blockIdx.x == 0 && tid == 0) g_pre = 0;

    // ---- stage: compute attn tile from raw dots + stats ----
    {
        const int r  = tid >> 5;               // 0..7
        const int c4 = tid & 31;               // 32 float4 per row
        const int gi = i0 + r;
        float4 s4 = reinterpret_cast<const float4*>(g_attn + (size_t)gi * P + j0)[c4];
        int4  n4  = reinterpret_cast<const int4*>(nei + (size_t)gi * P + j0)[c4];
        float4 hj = reinterpret_cast<const float4*>(g_hj + j0)[c4];
        const float hb  = g_hi[gi] + bptr[0];
        const float mx  = g_mx[gi];
        const float inv = g_inv[gi];

        float4 a;
        float pos;
        pos = s4.x + hj.x + hb; if (pos == 0.0f) pos = -1e-6f;
        a.x = (n4.x > 0) ? __expf(pos - mx) * inv : 0.0f;
        pos = s4.y + hj.y + hb; if (pos == 0.0f) pos = -1e-6f;
        a.y = (n4.y > 0) ? __expf(pos - mx) * inv : 0.0f;
        pos = s4.z + hj.z + hb; if (pos == 0.0f) pos = -1e-6f;
        a.z = (n4.z > 0) ? __expf(pos - mx) * inv : 0.0f;
        pos = s4.w + hj.w + hb; if (pos == 0.0f) pos = -1e-6f;
        a.w = (n4.w > 0) ? __expf(pos - mx) * inv : 0.0f;

        reinterpret_cast<float4*>(sat[r])[c4] = a;
    }
    __syncthreads();

    const int d  = tid & (MDIM - 1);
    const int jg = tid >> 6;                   // 0..3, 32 j's each
    float acc[ITILE];
    #pragma unroll
    for (int r = 0; r < ITILE; r++) acc[r] = 0.0f;

    #pragma unroll 8
    for (int jj = 0; jj < JTILE / 4; jj++) {
        int j = jg * (JTILE / 4) + jj;
        float h = __ldg(&hidden[(size_t)(j0 + j) * MDIM + d]);  // coalesced, L1/L2 hits
        #pragma unroll
        for (int r = 0; r < ITILE; r++) acc[r] = fmaf(sat[r][j], h, acc[r]);
    }
    #pragma unroll
    for (int r = 0; r < ITILE; r++) partb[jg][r][d] = acc[r];
    __syncthreads();

    // each thread finalizes 2 (r,d) outputs
    #pragma unroll
    for (int rr = 0; rr < 2; rr++) {
        int r = rr * 4 + jg;
        float v = partb[0][r][d] + partb[1][r][d] + partb[2][r][d] + partb[3][r][d];
        atomicAdd(&out[(size_t)(i0 + r) * MDIM + d], v);
    }
}

// ---------------------------------------------------------------------------
// Inputs (metadata order): 0 hidden_state f32[1024,64], 1 rela_state f32[1024,1024,64],
// 2 corr_index f32 (UNUSED), 3 nei_index i32[1024,1024], 4 W f32[192], 5 b f32[1].
// Output: f32[1024,64].
// ---------------------------------------------------------------------------
extern "C" void kernel_launch(void* const* d_in, const int* in_sizes, int n_in,
                              void* d_out, int out_size)
{
    const float* hidden = (const float*)d_in[0];
    const float* rela   = (const float*)d_in[1];
    const int*   nei    = (const int*)  d_in[3];
    const float* W      = (const float*)d_in[4];
    const float* b      = (const float*)d_in[5];
    float*       out    = (float*)d_out;

    stream_kernel<<<NPRE + NSTREAM, NTHR>>>(rela, hidden, nei, W, b, out);
    hsum_kernel<<<NIT * NJT, NTHR>>>(hidden, nei, b, out);
}

// round 14
// speedup vs baseline: 1.0746x; 1.0746x over previous
#include <cuda_runtime.h>
#include <cuda_bf16.h>

// Problem constants (match setup_inputs: P=1024, M=64, R=64)
#define P 1024
#define MDIM 64
#define RDIM 64
#define NTHR 256
#define PF 2       // software-pipeline depth (float4 buffers in flight)
#define QJ  256    // j's per stream block (quarter row)
#define NPRE    (P / 8)   // 128 precompute blocks at the FRONT of the grid
#define NSTREAM (P * 4)   // 4096 stream blocks

// hsum tiling
#define ITILE 8
#define JTILE 128
#define NJT   (P / JTILE)   // 8
#define NIT   (P / ITILE)   // 128

// Allocation-free scratch (__device__ globals)
__device__ float g_hi[P];
__device__ float g_hj[P];
__device__ float g_attn[P * P];   // 4 MB: RAW dots -> (in place) FINAL attn
__device__ int   g_rowcnt[P];     // quarters-done per row (reset by hsum)
__device__ int   g_pre;           // precompute-ready counter (reset by hsum)

// ---------------------------------------------------------------------------
// Kernel A: one grid, three roles.
//   blocks [0, 128):    precompute hi/hj (warp-per-row), zero d_out, then
//                       signal g_pre. Wave-1 guaranteed (front of grid),
//                       never waits -> no deadlock possible.
//   blocks [128, 4224): block = (row i, quarter q). Streams 64 KB of rela via
//                       __ldcs, writes 256 RAW dot values. The block that
//                       completes a row's 4th quarter computes the FULL
//                       softmax for that row and overwrites the raw dots with
//                       final attn — hidden under the DRAM stream of the
//                       remaining blocks.
// ---------------------------------------------------------------------------
__global__ __launch_bounds__(NTHR, 8) void stream_kernel(
    const float* __restrict__ rela,
    const float* __restrict__ hidden,
    const int*   __restrict__ nei,
    const float* __restrict__ W,
    const float* __restrict__ bptr,
    float* __restrict__ out)
{
    const int tid  = threadIdx.x;
    const int warp = tid >> 5;
    const int lane = tid & 31;

    if (blockIdx.x < NPRE) {
        // ---- precompute branch: hi/hj + zero d_out + ready signal ----
        const int pid = blockIdx.x;
        const int row = pid * 8 + warp;
        const int gid = pid * 256 + tid;             // 32768 threads

        reinterpret_cast<float2*>(out)[gid] = make_float2(0.0f, 0.0f);

        float2 h = reinterpret_cast<const float2*>(hidden + (size_t)row * MDIM)[lane];
        float wi0 = W[RDIM + lane * 2];
        float wi1 = W[RDIM + lane * 2 + 1];
        float wj0 = W[RDIM + MDIM + lane * 2];
        float wj1 = W[RDIM + MDIM + lane * 2 + 1];

        float si = h.x * wi0 + h.y * wi1;
        float sj = h.x * wj0 + h.y * wj1;
        #pragma unroll
        for (int off = 16; off >= 1; off >>= 1) {
            si += __shfl_xor_sync(0xFFFFFFFFu, si, off);
            sj += __shfl_xor_sync(0xFFFFFFFFu, sj, off);
        }
        if (lane == 0) {
            g_hi[row] = si;
            g_hj[row] = sj;
        }
        __threadfence();
        __syncthreads();
        if (tid == 0) atomicAdd(&g_pre, 1);
        return;
    }

    // ---- streaming branch ----
    __shared__ float part[QJ * 5];       // 4 partials per local j, padded (5 KB)
    __shared__ float red[8];
    __shared__ int   s_old;

    const int half = (lane >> 4);
    const int lh   = lane & 15;          // lane within half-warp
    const int hwid = warp * 2 + half;    // 0..15 half-warp id

    const int sid = blockIdx.x - NPRE;
    const int i   = sid >> 2;
    const int q   = sid & 3;
    const int j0  = q * QJ;

    {
        const float4 wv = __ldg(&reinterpret_cast<const float4*>(W)[lh]);
        // iteration k handles local j = k*16 + hwid; this thread reads float4 #lh
        const float4* p = reinterpret_cast<const float4*>(rela + (size_t)i * (P * RDIM))
                        + (size_t)(j0 + hwid) * 16 + lh;
        // stride per k: 16 j's * 16 float4 = 256 float4
        float4 buf[PF];
        #pragma unroll
        for (int qq = 0; qq < PF; qq++) buf[qq] = __ldcs(p + qq * 256);
        p += PF * 256;

        #pragma unroll
        for (int kk = 0; kk < (QJ / 16) / PF; kk++) {
            #pragma unroll
            for (int qq = 0; qq < PF; qq++) {
                float4 v = buf[qq];
                if (kk < (QJ / 16) / PF - 1) buf[qq] = __ldcs(p + qq * 256);
                float s = fmaf(v.x, wv.x, fmaf(v.y, wv.y, fmaf(v.z, wv.z, v.w * wv.w)));
                s += __shfl_xor_sync(0xFFFFFFFFu, s, 8);     // 16 -> 8
                s += __shfl_xor_sync(0xFFFFFFFFu, s, 4);     // 8 -> 4 partials
                const int jl = (kk * PF + qq) * 16 + hwid;
                if (lh < 4) part[jl * 5 + lh] = s;           // conflict-free (pad 5)
            }
            p += PF * 256;
        }
    }
    __syncthreads();

    // ---- finish: thread tid <-> local j = tid; write RAW dot ----
    {
        const float* pj = &part[tid * 5];          // stride 5: conflict-free
        float s = (pj[0] + pj[1]) + (pj[2] + pj[3]);
        g_attn[(size_t)i * P + j0 + tid] = s;      // coalesced 1 KB
    }

    // ---- quarter done: last block of the row does the FULL softmax ----
    __threadfence();
    __syncthreads();
    if (tid == 0) s_old = atomicAdd(&g_rowcnt[i], 1);
    __syncthreads();
    if (s_old != 3) return;

    // wait for hi/hj producers (wave-1 front blocks, guaranteed to run)
    if (tid == 0) {
        while (*(volatile int*)&g_pre < NPRE) __nanosleep(64);
    }
    __syncthreads();
    __threadfence();

    // whole row in registers: 256 threads x float4
    float4 v  = reinterpret_cast<const float4*>(g_attn + (size_t)i * P)[tid];
    int4  n4  = reinterpret_cast<const int4*>(nei + (size_t)i * P)[tid];
    float4 hj = reinterpret_cast<const float4*>(g_hj)[tid];
    const float hb = g_hi[i] + bptr[0];

    v.x = (n4.x > 0) ? (v.x + hj.x + hb) : 0.0f;  if (v.x == 0.0f) v.x = -1e-6f;
    v.y = (n4.y > 0) ? (v.y + hj.y + hb) : 0.0f;  if (v.y == 0.0f) v.y = -1e-6f;
    v.z = (n4.z > 0) ? (v.z + hj.z + hb) : 0.0f;  if (v.z == 0.0f) v.z = -1e-6f;
    v.w = (n4.w > 0) ? (v.w + hj.w + hb) : 0.0f;  if (v.w == 0.0f) v.w = -1e-6f;

    float mx = fmaxf(fmaxf(v.x, v.y), fmaxf(v.z, v.w));
    #pragma unroll
    for (int off = 16; off >= 1; off >>= 1)
        mx = fmaxf(mx, __shfl_xor_sync(0xFFFFFFFFu, mx, off));
    if (lane == 0) red[warp] = mx;
    __syncthreads();
    {
        float m = red[0];
        #pragma unroll
        for (int w = 1; w < 8; w++) m = fmaxf(m, red[w]);
        mx = m;
    }
    __syncthreads();

    float4 e;
    e.x = __expf(v.x - mx);
    e.y = __expf(v.y - mx);
    e.z = __expf(v.z - mx);
    e.w = __expf(v.w - mx);
    float sum = (e.x + e.y) + (e.z + e.w);
    #pragma unroll
    for (int off = 16; off >= 1; off >>= 1)
        sum += __shfl_xor_sync(0xFFFFFFFFu, sum, off);
    if (lane == 0) red[warp] = sum;
    __syncthreads();
    float inv;
    {
        float s = 0.0f;
        #pragma unroll
        for (int w = 0; w < 8; w++) s += red[w];
        inv = 1.0f / s;
    }

    // overwrite raw dots with FINAL attn (this block owns the row)
    float4 a;
    a.x = (n4.x > 0) ? e.x * inv : 0.0f;
    a.y = (n4.y > 0) ? e.y * inv : 0.0f;
    a.z = (n4.z > 0) ? e.z * inv : 0.0f;
    a.w = (n4.w > 0) ? e.w * inv : 0.0f;
    reinterpret_cast<float4*>(g_attn + (size_t)i * P)[tid] = a;
}

// ---------------------------------------------------------------------------
// Kernel B: H_sum = attn @ hidden. 128 i-tiles (8 rows) x 8 j-tiles = 1024
// blocks. Plain copy-stage (attn is final). Main loop: float2 per thread,
// 8 j-groups of 16 -> 0.6 MAC/instr. Resets counters for the next replay.
// ---------------------------------------------------------------------------
__global__ __launch_bounds__(NTHR) void hsum_kernel(
    const float* __restrict__ hidden,
    float*       __restrict__ out)
{
    __shared__ float sat[ITILE][JTILE];            // 4 KB (attn tile)
    __shared__ float partb[8][ITILE][MDIM];        // 16 KB

    const int tid = threadIdx.x;
    const int it  = blockIdx.x >> 3;          // 0..127
    const int jt  = blockIdx.x & 7;           // 0..7
    const int i0  = it * ITILE;
    const int j0  = jt * JTILE;

    // reset counters for the next replay (this kernel always runs last)
    if (jt == 0 && tid < ITILE) g_rowcnt[i0 + tid] = 0;
    if (blockIdx.x == 0 && tid == 0) g_pre = 0;

    // stage attn tile: 256 float4, 1 per thread, coalesced, plain copy
    {
        const int r  = tid >> 5;               // 0..7
        const int c4 = tid & 31;               // 32 float4 per row
        reinterpret_cast<float4*>(sat[r])[c4] =
            reinterpret_cast<const float4*>(g_attn + (size_t)(i0 + r) * P + j0)[c4];
    }
    __syncthreads();

    // main: thread = (d-pair d2 = tid&31, j-group jg = tid>>5 of 16 j's)
    const int d2 = tid & 31;                   // covers d = 2*d2, 2*d2+1
    const int jg = tid >> 5;                   // 0..7 (uniform per warp)
    const float2* hidden2 = reinterpret_cast<const float2*>(hidden);

    float2 acc[ITILE];
    #pragma unroll
    for (int r = 0; r < ITILE; r++) acc[r] = make_float2(0.0f, 0.0f);

    #pragma unroll
    for (int jj = 0; jj < 16; jj++) {
        const int j = jg * 16 + jj;
        float2 h = hidden2[(size_t)(j0 + j) * 32 + d2];   // coalesced 256 B/warp
        #pragma unroll
        for (int r = 0; r < ITILE; r++) {
            float a = sat[r][j];               // uniform per warp: LDS broadcast
            acc[r].x = fmaf(a, h.x, acc[r].x);
            acc[r].y = fmaf(a, h.y, acc[r].y);
        }
    }
    #pragma unroll
    for (int r = 0; r < ITILE; r++)
        reinterpret_cast<float2*>(partb[jg][r])[d2] = acc[r];
    __syncthreads();

    // reduce 8 jg partials; 512 outputs, 2 per thread; d=tid&63 -> conflict-free
    #pragma unroll
    for (int oo = 0; oo < 2; oo++) {
        const int o = oo * NTHR + tid;
        const int r = o >> 6;
        const int d = o & 63;
        float s = ((partb[0][r][d] + partb[1][r][d]) + (partb[2][r][d] + partb[3][r][d]))
                + ((partb[4][r][d] + partb[5][r][d]) + (partb[6][r][d] + partb[7][r][d]));
        atomicAdd(&out[(size_t)(i0 + r) * MDIM + d], s);
    }
}

// ---------------------------------------------------------------------------
// Inputs (metadata order): 0 hidden_state f32[1024,64], 1 rela_state f32[1024,1024,64],
// 2 corr_index f32 (UNUSED), 3 nei_index i32[1024,1024], 4 W f32[192], 5 b f32[1].
// Output: f32[1024,64].
// ---------------------------------------------------------------------------
extern "C" void kernel_launch(void* const* d_in, const int* in_sizes, int n_in,
                              void* d_out, int out_size)
{
    const float* hidden = (const float*)d_in[0];
    const float* rela   = (const float*)d_in[1];
    const int*   nei    = (const int*)  d_in[3];
    const float* W      = (const float*)d_in[4];
    const float* b      = (const float*)d_in[5];
    float*       out    = (float*)d_out;

    stream_kernel<<<NPRE + NSTREAM, NTHR>>>(rela, hidden, nei, W, b, out);
    hsum_kernel<<<NIT * NJT, NTHR>>>(hidden, out);
}